// round 6
// baseline (speedup 1.0000x reference)
#include <cuda_runtime.h>
#include <cstdint>
#include <cstddef>

#define T_STEPS 2048
#define BATCH   32
#define DIM     512
#define HID     512
#define GATES   2048   // 4*HID

typedef unsigned long long ull;

// 512 MB scratch for gx = x @ w_ih^T + b_ih + b_hh
__device__ float g_gx[134217728];  // T_STEPS*BATCH*GATES

// double-buffered transposed hidden state h_T[buf][u][b]
__device__ __align__(16) float g_ht[2][HID * BATCH];

// single monotonic step counter (128 releases per step)
__device__ unsigned int g_cnt;

// ---------------- packed f32x2 helpers (Blackwell FFMA2 path) ----------------
__device__ __forceinline__ void ffma2(ull& d, ull a, ull b) {
    asm("fma.rn.f32x2 %0, %1, %2, %0;" : "+l"(d) : "l"(a), "l"(b));
}
__device__ __forceinline__ ull addf2(ull a, ull b) {
    ull r; asm("add.rn.f32x2 %0, %1, %2;" : "=l"(r) : "l"(a), "l"(b)); return r;
}
__device__ __forceinline__ ull pk2(float x, float y) {
    ull r; asm("mov.b64 %0, {%1, %2};" : "=l"(r) : "f"(x), "f"(y)); return r;
}
__device__ __forceinline__ float2 upk(ull v) {
    float2 r; asm("mov.b64 {%0, %1}, %2;" : "=f"(r.x), "=f"(r.y) : "l"(v)); return r;
}

// ---------------------------------------------------------------------------
// Kernel 1: gx[r][n] = sum_k X[r][k]*W[n][k] + bih[n] + bhh[n]
// ---------------------------------------------------------------------------
__global__ void __launch_bounds__(256, 2) gemm_gx(
    const float* __restrict__ X,
    const float* __restrict__ W,
    const float* __restrict__ bih,
    const float* __restrict__ bhh)
{
    __shared__ float As[2][8][128];
    __shared__ float Bs[2][8][128];

    const int bm  = blockIdx.y * 128;
    const int bn  = blockIdx.x * 128;
    const int tid = threadIdx.x;
    const int tx  = tid & 15;
    const int ty  = tid >> 4;

    ull acc2[4][8];
#pragma unroll
    for (int i = 0; i < 4; i++)
#pragma unroll
        for (int j = 0; j < 8; j++) acc2[i][j] = 0ull;

    const int lr = tid >> 1;
    const int lk = (tid & 1) * 4;
    const float* Ap = X + (size_t)(bm + lr) * DIM + lk;
    const float* Bp = W + (size_t)(bn + lr) * DIM + lk;

    {
        float4 av = *(const float4*)Ap;
        float4 bv = *(const float4*)Bp;
        As[0][lk + 0][lr] = av.x; As[0][lk + 1][lr] = av.y;
        As[0][lk + 2][lr] = av.z; As[0][lk + 3][lr] = av.w;
        Bs[0][lk + 0][lr] = bv.x; Bs[0][lk + 1][lr] = bv.y;
        Bs[0][lk + 2][lr] = bv.z; Bs[0][lk + 3][lr] = bv.w;
    }
    __syncthreads();

    const int NSLAB = DIM / 8;
    for (int s = 0; s < NSLAB; s++) {
        const int buf = s & 1;
        float4 avn, bvn;
        if (s + 1 < NSLAB) {
            avn = *(const float4*)(Ap + (s + 1) * 8);
            bvn = *(const float4*)(Bp + (s + 1) * 8);
        }
#pragma unroll
        for (int kk = 0; kk < 8; kk++) {
            const ulonglong2* a01 = (const ulonglong2*)&As[buf][kk][ty * 8];
            ulonglong2 al = a01[0];
            ulonglong2 ah = a01[1];
            ull a2[4] = { al.x, al.y, ah.x, ah.y };
            float4 b0 = *(const float4*)&Bs[buf][kk][tx * 8];
            float4 b1 = *(const float4*)&Bs[buf][kk][tx * 8 + 4];
            ull bd[8] = { pk2(b0.x, b0.x), pk2(b0.y, b0.y),
                          pk2(b0.z, b0.z), pk2(b0.w, b0.w),
                          pk2(b1.x, b1.x), pk2(b1.y, b1.y),
                          pk2(b1.z, b1.z), pk2(b1.w, b1.w) };
#pragma unroll
            for (int i2 = 0; i2 < 4; i2++)
#pragma unroll
                for (int j = 0; j < 8; j++)
                    ffma2(acc2[i2][j], a2[i2], bd[j]);
        }
        if (s + 1 < NSLAB) {
            const int nb = buf ^ 1;
            As[nb][lk + 0][lr] = avn.x; As[nb][lk + 1][lr] = avn.y;
            As[nb][lk + 2][lr] = avn.z; As[nb][lk + 3][lr] = avn.w;
            Bs[nb][lk + 0][lr] = bvn.x; Bs[nb][lk + 1][lr] = bvn.y;
            Bs[nb][lk + 2][lr] = bvn.z; Bs[nb][lk + 3][lr] = bvn.w;
            __syncthreads();
        }
    }

    const int row0 = bm + ty * 8;
    const int col0 = bn + tx * 8;
    float bias[8];
#pragma unroll
    for (int j = 0; j < 8; j++) bias[j] = bih[col0 + j] + bhh[col0 + j];

#pragma unroll
    for (int i = 0; i < 8; i++) {
        const int i2 = i >> 1;
        const int s  = i & 1;
        float v[8];
#pragma unroll
        for (int j = 0; j < 8; j++) {
            float2 p = upk(acc2[i2][j]);
            v[j] = (s ? p.y : p.x) + bias[j];
        }
        float* dst = &g_gx[(size_t)(row0 + i) * GATES + col0];
        float4 v0 = { v[0], v[1], v[2], v[3] };
        float4 v1 = { v[4], v[5], v[6], v[7] };
        *(float4*)dst       = v0;
        *(float4*)(dst + 4) = v1;
    }
}

// ---------------------------------------------------------------------------
// init: reset counter + transpose h0 into g_ht[1][u][b]  (step 0 reads buf 1)
// ---------------------------------------------------------------------------
__global__ void init_rec(const float* __restrict__ h0)
{
    int i = blockIdx.x * 256 + threadIdx.x;   // 0..16383
    if (i == 0) g_cnt = 0u;
    int b = i >> 9;
    int u = i & 511;
    g_ht[1][u * BATCH + b] = h0[i];
}

// ---------------------------------------------------------------------------
// Kernel 2: persistent recurrence. 128 blocks x 256 threads (8 warps).
//   Warp-autonomous: warp owns 16 cols x 4 batches; K split across lanes
//   (lane = kq*4 + j, kq: K-slice of 64, j: batch). Shuffle reduction over kq,
//   in-register c-state, in-warp epilogue. One syncthreads + release per step.
// ---------------------------------------------------------------------------
#define RBLK 128
#define RTHR 256
#define SECW 1028                    // 64*16 + 4 floats: kq-section skew (bank spread)
// smem floats: WT[8*1028] = 8224
#define SMEM_FLOATS (8 * SECW)

__global__ void __launch_bounds__(RTHR, 1) lstm_rec(
    const float* __restrict__ c0,
    const float* __restrict__ whh,
    float* __restrict__ out, float* __restrict__ hn, float* __restrict__ cn)
{
    extern __shared__ float sm[];
    float* WT = sm;                  // [kq:8] sections of [i:64][c:16], stride SECW

    const int tid = threadIdx.x;
    const int u0  = blockIdx.x * 4;

    // load w_hh slice: col c = uu*4+gate  (unit-major) <-> row gate*512 + u0+uu
    for (int idx = tid; idx < 8192; idx += RTHR) {
        int c    = idx & 15;
        int k    = idx >> 4;
        int kq   = k >> 6;
        int i    = k & 63;
        int uu   = c >> 2;
        int gate = c & 3;
        int grow = gate * HID + u0 + uu;
        WT[kq * SECW + i * 16 + c] = whh[(size_t)grow * HID + k];
    }
    __syncthreads();

    const int w  = tid >> 5;         // warp 0..7: batches 4w..4w+3
    const int ln = tid & 31;
    const int kq = ln >> 2;          // K-slice 0..7 (64 k each)
    const int j  = ln & 3;           // batch within warp group
    const int bb = 4 * w + j;        // this lane's batch

    const bool epi = (kq < 4);       // epilogue lanes: unit uu = kq
    const int  uu  = kq;             // (only meaningful when epi)
    const int  uo  = u0 + uu;

    // in-register cell state
    float creg = 0.f;
    if (epi) creg = c0[bb * HID + uo];

    // gx prefetch for t=0
    float gxv[4];
    if (epi) {
        const size_t base = (size_t)bb * GATES;
#pragma unroll
        for (int g = 0; g < 4; g++)
            gxv[g] = g_gx[base + g * HID + uo];
    }

    const float* wt_base = WT + kq * SECW;

    for (int t = 0; t < T_STEPS; t++) {
        const int rb = (t & 1) ^ 1;    // read buffer (h_{t-1})
        const int wb = t & 1;          // write buffer (h_t)

        // per-warp wait: all 128 blocks published h_{t-1}
        if (t > 0) {
            if (ln == 0) {
                const unsigned tgt = 128u * (unsigned)t;
                unsigned v;
                do {
                    asm volatile("ld.acquire.gpu.global.u32 %0, [%1];"
                                 : "=r"(v) : "l"(&g_cnt) : "memory");
                } while (v < tgt);
            }
            __syncwarp();
        }

        // GEMM: lane does K=64 for 16 cols, 1 batch. acc pairs c=(2p,2p+1).
        ull acc2[8];
#pragma unroll
        for (int p = 0; p < 8; p++) acc2[p] = 0ull;

        const float* hp = g_ht[rb] + (kq * 64) * BATCH + bb;
        const float* wp = wt_base;
#pragma unroll 16
        for (int k = 0; k < 64; k++) {
            float hv = __ldcg(hp); hp += BATCH;
            ull hd = pk2(hv, hv);
            ulonglong2 q0 = *(const ulonglong2*)(wp);
            ulonglong2 q1 = *(const ulonglong2*)(wp + 4);
            ulonglong2 q2 = *(const ulonglong2*)(wp + 8);
            ulonglong2 q3 = *(const ulonglong2*)(wp + 12);
            wp += 16;
            ffma2(acc2[0], hd, q0.x); ffma2(acc2[1], hd, q0.y);
            ffma2(acc2[2], hd, q1.x); ffma2(acc2[3], hd, q1.y);
            ffma2(acc2[4], hd, q2.x); ffma2(acc2[5], hd, q2.y);
            ffma2(acc2[6], hd, q3.x); ffma2(acc2[7], hd, q3.y);
        }

        // reduce over kq (lane bits 2..4): xor 4, 8, 16
#pragma unroll
        for (int mask = 4; mask <= 16; mask <<= 1) {
#pragma unroll
            for (int p = 0; p < 8; p++) {
                ull o = __shfl_xor_sync(0xffffffffu, acc2[p], mask);
                acc2[p] = addf2(acc2[p], o);
            }
        }

        // in-warp epilogue: lanes kq<4 handle unit uu=kq, batch bb
        if (epi) {
            float2 pif = upk(acc2[2 * uu]);      // gates i, f  (c = 4uu, 4uu+1)
            float2 pgo = upk(acc2[2 * uu + 1]);  // gates g, o
            float iv = pif.x + gxv[0];
            float fv = pif.y + gxv[1];
            float gv = pgo.x + gxv[2];
            float ov = pgo.y + gxv[3];
            float it = 1.f / (1.f + __expf(-iv));
            float ft = 1.f / (1.f + __expf(-fv));
            float gt = tanhf(gv);
            float ot = 1.f / (1.f + __expf(-ov));
            creg = ft * creg + it * gt;
            float hv = ot * tanhf(creg);
            g_ht[wb][uo * BATCH + bb] = hv;      // publish h_t (transposed)
            out[(size_t)t * BATCH * HID + bb * HID + uo] = hv;
            if (t == T_STEPS - 1) {
                hn[bb * HID + uo] = hv;
                cn[bb * HID + uo] = creg;
            }
        }

        // prefetch gx for t+1 (off critical path)
        if (epi && t + 1 < T_STEPS) {
            const size_t base = ((size_t)(t + 1) * BATCH + bb) * GATES;
#pragma unroll
            for (int g = 0; g < 4; g++)
                gxv[g] = g_gx[base + g * HID + uo];
        }

        // block-wide publish, then single release
        if (t < T_STEPS - 1) {
            __syncthreads();
            if (tid == 0) {
                asm volatile("red.release.gpu.global.add.u32 [%0], 1;"
                             :: "l"(&g_cnt) : "memory");
            }
        }
    }
}

// ---------------------------------------------------------------------------
extern "C" void kernel_launch(void* const* d_in, const int* in_sizes, int n_in,
                              void* d_out, int out_size)
{
    const float* x   = (const float*)d_in[0];
    const float* h0  = (const float*)d_in[1];
    const float* c0  = (const float*)d_in[2];
    const float* wih = (const float*)d_in[3];
    const float* bih = (const float*)d_in[4];
    const float* whh = (const float*)d_in[5];
    const float* bhh = (const float*)d_in[6];

    float* out = (float*)d_out;
    float* hn  = out + (size_t)T_STEPS * BATCH * HID;
    float* cn  = hn + BATCH * HID;

    init_rec<<<64, 256>>>(h0);
    gemm_gx<<<dim3(GATES / 128, (T_STEPS * BATCH) / 128), 256>>>(x, wih, bih, bhh);

    const size_t shmem = SMEM_FLOATS * sizeof(float);
    cudaFuncSetAttribute(lstm_rec, cudaFuncAttributeMaxDynamicSharedMemorySize, (int)shmem);
    lstm_rec<<<RBLK, RTHR, shmem>>>(c0, whh, out, hn, cn);
}

// round 7
// speedup vs baseline: 1.4434x; 1.4434x over previous
#include <cuda_runtime.h>
#include <cstdint>
#include <cstddef>

#define T_STEPS 2048
#define BATCH   32
#define DIM     512
#define HID     512
#define GATES   2048   // 4*HID

typedef unsigned long long ull;

// 512 MB scratch for gx = x @ w_ih^T + b_ih + b_hh
__device__ float g_gx[134217728];  // T_STEPS*BATCH*GATES

// double-buffered transposed hidden state h_T[buf][u][b]
__device__ __align__(16) float g_ht[2][HID * BATCH];

// monotonic release counter: 4 epi-warp releases per block per step -> 512/step
__device__ unsigned int g_cnt;

// ---------------- packed f32x2 helpers (Blackwell FFMA2 path) ----------------
__device__ __forceinline__ void ffma2(ull& d, ull a, ull b) {
    asm("fma.rn.f32x2 %0, %1, %2, %0;" : "+l"(d) : "l"(a), "l"(b));
}
__device__ __forceinline__ ull addf2(ull a, ull b) {
    ull r; asm("add.rn.f32x2 %0, %1, %2;" : "=l"(r) : "l"(a), "l"(b)); return r;
}
__device__ __forceinline__ ull pk2(float x, float y) {
    ull r; asm("mov.b64 %0, {%1, %2};" : "=l"(r) : "f"(x), "f"(y)); return r;
}
__device__ __forceinline__ float2 upk(ull v) {
    float2 r; asm("mov.b64 {%0, %1}, %2;" : "=f"(r.x), "=f"(r.y) : "l"(v)); return r;
}

// ---------------------------------------------------------------------------
// Kernel 1: gx[r][n] = sum_k X[r][k]*W[n][k] + bih[n] + bhh[n]
// ---------------------------------------------------------------------------
__global__ void __launch_bounds__(256, 2) gemm_gx(
    const float* __restrict__ X,
    const float* __restrict__ W,
    const float* __restrict__ bih,
    const float* __restrict__ bhh)
{
    __shared__ float As[2][8][128];
    __shared__ float Bs[2][8][128];

    const int bm  = blockIdx.y * 128;
    const int bn  = blockIdx.x * 128;
    const int tid = threadIdx.x;
    const int tx  = tid & 15;
    const int ty  = tid >> 4;

    ull acc2[4][8];
#pragma unroll
    for (int i = 0; i < 4; i++)
#pragma unroll
        for (int j = 0; j < 8; j++) acc2[i][j] = 0ull;

    const int lr = tid >> 1;
    const int lk = (tid & 1) * 4;
    const float* Ap = X + (size_t)(bm + lr) * DIM + lk;
    const float* Bp = W + (size_t)(bn + lr) * DIM + lk;

    {
        float4 av = *(const float4*)Ap;
        float4 bv = *(const float4*)Bp;
        As[0][lk + 0][lr] = av.x; As[0][lk + 1][lr] = av.y;
        As[0][lk + 2][lr] = av.z; As[0][lk + 3][lr] = av.w;
        Bs[0][lk + 0][lr] = bv.x; Bs[0][lk + 1][lr] = bv.y;
        Bs[0][lk + 2][lr] = bv.z; Bs[0][lk + 3][lr] = bv.w;
    }
    __syncthreads();

    const int NSLAB = DIM / 8;
    for (int s = 0; s < NSLAB; s++) {
        const int buf = s & 1;
        float4 avn, bvn;
        if (s + 1 < NSLAB) {
            avn = *(const float4*)(Ap + (s + 1) * 8);
            bvn = *(const float4*)(Bp + (s + 1) * 8);
        }
#pragma unroll
        for (int kk = 0; kk < 8; kk++) {
            const ulonglong2* a01 = (const ulonglong2*)&As[buf][kk][ty * 8];
            ulonglong2 al = a01[0];
            ulonglong2 ah = a01[1];
            ull a2[4] = { al.x, al.y, ah.x, ah.y };
            float4 b0 = *(const float4*)&Bs[buf][kk][tx * 8];
            float4 b1 = *(const float4*)&Bs[buf][kk][tx * 8 + 4];
            ull bd[8] = { pk2(b0.x, b0.x), pk2(b0.y, b0.y),
                          pk2(b0.z, b0.z), pk2(b0.w, b0.w),
                          pk2(b1.x, b1.x), pk2(b1.y, b1.y),
                          pk2(b1.z, b1.z), pk2(b1.w, b1.w) };
#pragma unroll
            for (int i2 = 0; i2 < 4; i2++)
#pragma unroll
                for (int j = 0; j < 8; j++)
                    ffma2(acc2[i2][j], a2[i2], bd[j]);
        }
        if (s + 1 < NSLAB) {
            const int nb = buf ^ 1;
            As[nb][lk + 0][lr] = avn.x; As[nb][lk + 1][lr] = avn.y;
            As[nb][lk + 2][lr] = avn.z; As[nb][lk + 3][lr] = avn.w;
            Bs[nb][lk + 0][lr] = bvn.x; Bs[nb][lk + 1][lr] = bvn.y;
            Bs[nb][lk + 2][lr] = bvn.z; Bs[nb][lk + 3][lr] = bvn.w;
            __syncthreads();
        }
    }

    const int row0 = bm + ty * 8;
    const int col0 = bn + tx * 8;
    float bias[8];
#pragma unroll
    for (int j = 0; j < 8; j++) bias[j] = bih[col0 + j] + bhh[col0 + j];

#pragma unroll
    for (int i = 0; i < 8; i++) {
        const int i2 = i >> 1;
        const int s  = i & 1;
        float v[8];
#pragma unroll
        for (int j = 0; j < 8; j++) {
            float2 p = upk(acc2[i2][j]);
            v[j] = (s ? p.y : p.x) + bias[j];
        }
        float* dst = &g_gx[(size_t)(row0 + i) * GATES + col0];
        float4 v0 = { v[0], v[1], v[2], v[3] };
        float4 v1 = { v[4], v[5], v[6], v[7] };
        *(float4*)dst       = v0;
        *(float4*)(dst + 4) = v1;
    }
}

// ---------------------------------------------------------------------------
// init: reset counter + transpose h0 into g_ht[1][u][b]  (step 0 reads buf 1)
// ---------------------------------------------------------------------------
__global__ void init_rec(const float* __restrict__ h0)
{
    int i = blockIdx.x * 256 + threadIdx.x;   // 0..16383
    if (i == 0) g_cnt = 0u;
    int b = i >> 9;
    int u = i & 511;
    g_ht[1][u * BATCH + b] = h0[i];
}

// ---------------------------------------------------------------------------
// Kernel 2: persistent recurrence, warp-specialized.
//   128 blocks x 384 threads: warps 0..7 = GEMM producers (R5 layout),
//   warps 8..11 = epilogue consumers (one unit each, c-state in registers).
//   Handoff via named barrier 1 (count 384); RED double-buffered by parity.
// ---------------------------------------------------------------------------
#define RBLK 128
#define RTHR 384
// smem floats: WT[512*16]=8192 | RED[2][8*576]=9216
#define SMEM_FLOATS (8192 + 2 * 4608)
#define SMEM_BYTES  122880   // pad request to force 1 block/SM

__global__ void __launch_bounds__(RTHR, 1) lstm_rec(
    const float* __restrict__ c0,
    const float* __restrict__ whh,
    float* __restrict__ out, float* __restrict__ hn, float* __restrict__ cn)
{
    extern __shared__ float sm[];
    float* WT  = sm;             // [k:512][c:16]
    float* RED = sm + 8192;      // [buf:2][ks:8][b*18 + c]

    const int tid = threadIdx.x;
    const int u0  = blockIdx.x * 4;

    // load w_hh slice: local col c = uu*4+gate <-> global row gate*512 + u0+uu
    for (int idx = tid; idx < 8192; idx += RTHR) {
        int c    = idx & 15;
        int k    = idx >> 4;
        int uu   = c >> 2;
        int gate = c & 3;
        int grow = gate * HID + u0 + uu;
        WT[idx] = whh[(size_t)grow * HID + k];
    }
    __syncthreads();

    if (tid < 256) {
        // ---------------- GEMM producer warps ----------------
        const int ks = tid >> 5;           // 0..7 K-slice (64 k each)
        const int ln = tid & 31;
        const int bq = ln & 7;             // batches 4bq..4bq+3
        const int cq = ln >> 3;            // cols 4cq..4cq+3

        const float* wbase = WT + (ks * 64) * 16 + cq * 4;

        for (int t = 0; t < T_STEPS; t++) {
            const int rb = (t & 1) ^ 1;

            if (t > 0) {
                if (ln == 0) {
                    const unsigned tgt = 512u * (unsigned)t;
                    unsigned v;
                    do {
                        asm volatile("ld.acquire.gpu.global.u32 %0, [%1];"
                                     : "=r"(v) : "l"(&g_cnt) : "memory");
                    } while (v < tgt);
                }
                __syncwarp();
            }

            ull acc2[4][2];
#pragma unroll
            for (int i = 0; i < 4; i++) { acc2[i][0] = 0ull; acc2[i][1] = 0ull; }

            const float4* hp = (const float4*)(g_ht[rb] + (ks * 64) * BATCH + bq * 4);
            const float*  wp = wbase;
#pragma unroll 16
            for (int k = 0; k < 64; k++) {
                float4 hv = __ldcg(hp); hp += 8;       // +32 floats (one row)
                ulonglong2 wq = *(const ulonglong2*)wp; wp += 16;
                ull h0d = pk2(hv.x, hv.x);
                ull h1d = pk2(hv.y, hv.y);
                ull h2d = pk2(hv.z, hv.z);
                ull h3d = pk2(hv.w, hv.w);
                ffma2(acc2[0][0], h0d, wq.x); ffma2(acc2[0][1], h0d, wq.y);
                ffma2(acc2[1][0], h1d, wq.x); ffma2(acc2[1][1], h1d, wq.y);
                ffma2(acc2[2][0], h2d, wq.x); ffma2(acc2[2][1], h2d, wq.y);
                ffma2(acc2[3][0], h3d, wq.x); ffma2(acc2[3][1], h3d, wq.y);
            }

            // write partials into this step's RED buffer
            {
                float* rbuf = RED + (t & 1) * 4608 + ks * 576;
#pragma unroll
                for (int bb = 0; bb < 4; bb++) {
                    ull* rp = (ull*)(rbuf + (4 * bq + bb) * 18 + 4 * cq);
                    rp[0] = acc2[bb][0];
                    rp[1] = acc2[bb][1];
                }
            }
            // signal consumers (membar.cta semantics included)
            asm volatile("bar.arrive 1, 384;" ::: "memory");
        }
    } else {
        // ---------------- epilogue consumer warps ----------------
        const int etid = tid - 256;        // 0..127
        const int euu  = etid >> 5;        // unit index 0..3 (one per warp)
        const int ebb  = etid & 31;        // batch = lane
        const int uo   = u0 + euu;
        const int ln   = etid & 31;

        float creg = c0[ebb * HID + uo];

        float gxv[4];
        {
            const size_t base = (size_t)ebb * GATES;
#pragma unroll
            for (int g = 0; g < 4; g++)
                gxv[g] = g_gx[base + g * HID + uo];
        }

        for (int t = 0; t < T_STEPS; t++) {
            asm volatile("bar.sync 1, 384;" ::: "memory");

            const ull* q = (const ull*)(RED + (t & 1) * 4608 + ebb * 18 + euu * 4);
            ull s01 = 0ull, s23 = 0ull;
#pragma unroll
            for (int kq = 0; kq < 8; kq++) {
                s01 = addf2(s01, q[0]);
                s23 = addf2(s23, q[1]);
                q += 288;   // 576 floats
            }
            float2 p01 = upk(s01);
            float2 p23 = upk(s23);
            float iv = p01.x + gxv[0];
            float fv = p01.y + gxv[1];
            float gv = p23.x + gxv[2];
            float ov = p23.y + gxv[3];
            float it = 1.f / (1.f + __expf(-iv));
            float ft = 1.f / (1.f + __expf(-fv));
            float gt = tanhf(gv);
            float ot = 1.f / (1.f + __expf(-ov));
            creg = ft * creg + it * gt;
            float hv = ot * tanhf(creg);

            // publish h_t (coalesced: one 128B line per warp)
            g_ht[t & 1][uo * BATCH + ebb] = hv;
            __syncwarp();
            if (ln == 0 && t < T_STEPS - 1) {
                asm volatile("red.release.gpu.global.add.u32 [%0], 1;"
                             :: "l"(&g_cnt) : "memory");
            }

            // off-critical-path work
            out[(size_t)t * BATCH * HID + ebb * HID + uo] = hv;
            if (t + 1 < T_STEPS) {
                const size_t base = ((size_t)(t + 1) * BATCH + ebb) * GATES;
#pragma unroll
                for (int g = 0; g < 4; g++)
                    gxv[g] = g_gx[base + g * HID + uo];
            } else {
                hn[ebb * HID + uo] = hv;
                cn[ebb * HID + uo] = creg;
            }
        }
    }
}

// ---------------------------------------------------------------------------
extern "C" void kernel_launch(void* const* d_in, const int* in_sizes, int n_in,
                              void* d_out, int out_size)
{
    const float* x   = (const float*)d_in[0];
    const float* h0  = (const float*)d_in[1];
    const float* c0  = (const float*)d_in[2];
    const float* wih = (const float*)d_in[3];
    const float* bih = (const float*)d_in[4];
    const float* whh = (const float*)d_in[5];
    const float* bhh = (const float*)d_in[6];

    float* out = (float*)d_out;
    float* hn  = out + (size_t)T_STEPS * BATCH * HID;
    float* cn  = hn + BATCH * HID;

    init_rec<<<64, 256>>>(h0);
    gemm_gx<<<dim3(GATES / 128, (T_STEPS * BATCH) / 128), 256>>>(x, wih, bih, bhh);

    cudaFuncSetAttribute(lstm_rec, cudaFuncAttributeMaxDynamicSharedMemorySize, SMEM_BYTES);
    lstm_rec<<<RBLK, RTHR, SMEM_BYTES>>>(c0, whh, out, hn, cn);
}

// round 9
// speedup vs baseline: 1.6288x; 1.1284x over previous
#include <cuda_runtime.h>
#include <cstdint>
#include <cstddef>

#define T_STEPS 2048
#define BATCH   32
#define DIM     512
#define HID     512
#define GATES   2048   // 4*HID

typedef unsigned long long ull;

// 512 MB scratch for gx = x @ w_ih^T + b_ih + b_hh
__device__ float g_gx[134217728];  // T_STEPS*BATCH*GATES

// double-buffered transposed hidden state h_T[buf][u][b]
__device__ __align__(16) float g_ht[2][HID * BATCH];

// rec step counter (128 releases per step)
__device__ unsigned int g_cnt;
// gx tile readiness: y-tile yt (rows [128yt,128yt+128) = timesteps [4yt,4yt+4)) ready when == 16
__device__ unsigned int g_ycnt[512];

// ---------------- packed f32x2 helpers (Blackwell FFMA2 path) ----------------
__device__ __forceinline__ void ffma2(ull& d, ull a, ull b) {
    asm("fma.rn.f32x2 %0, %1, %2, %0;" : "+l"(d) : "l"(a), "l"(b));
}
__device__ __forceinline__ ull addf2(ull a, ull b) {
    ull r; asm("add.rn.f32x2 %0, %1, %2;" : "=l"(r) : "l"(a), "l"(b)); return r;
}
__device__ __forceinline__ ull pk2(float x, float y) {
    ull r; asm("mov.b64 %0, {%1, %2};" : "=l"(r) : "f"(x), "f"(y)); return r;
}
__device__ __forceinline__ float2 upk(ull v) {
    float2 r; asm("mov.b64 {%0, %1}, %2;" : "=f"(r.x), "=f"(r.y) : "l"(v)); return r;
}
__device__ __forceinline__ unsigned ld_acq(const unsigned* p) {
    unsigned v;
    asm volatile("ld.acquire.gpu.global.u32 %0, [%1];" : "=r"(v) : "l"(p) : "memory");
    return v;
}

// ---------------------------------------------------------------------------
// init: reset counters + transpose h0 into g_ht[1][u][b]  (step 0 reads buf 1)
// ---------------------------------------------------------------------------
__global__ void init_rec(const float* __restrict__ h0)
{
    int i = blockIdx.x * 256 + threadIdx.x;   // 0..16383
    if (i == 0) g_cnt = 0u;
    if (i < 512) g_ycnt[i] = 0u;
    int b = i >> 9;
    int u = i & 511;
    g_ht[1][u * BATCH + b] = h0[i];
}

// ---------------------------------------------------------------------------
// MEGA kernel: bids 0..127 = persistent recurrence (R5 core);
//              bids 128..8319 = one gx GEMM tile each, released via g_ycnt.
// ---------------------------------------------------------------------------
#define RBLK 128
#define NTILE 8192           // 16 x-tiles * 512 y-tiles
// rec smem floats: WT[512*16]=8192 | RED[8*576]=4608 | CS[128]  = 12928
// gemm smem floats: As[2][8][128] + Bs[2][8][128]               =  4096
#define SMEM_FLOATS 12928

__global__ void __launch_bounds__(256, 2) mega(
    const float* __restrict__ X,     // x [T*B, D]
    const float* __restrict__ Wih,   // [4H, D]
    const float* __restrict__ bih,
    const float* __restrict__ bhh,
    const float* __restrict__ c0,
    const float* __restrict__ whh,
    float* __restrict__ out, float* __restrict__ hn, float* __restrict__ cn)
{
    extern __shared__ float sm[];
    const int tid = threadIdx.x;

    if (blockIdx.x >= RBLK) {
        // ==================== gx GEMM tile ====================
        const int gid = blockIdx.x - RBLK;
        const int bn  = (gid & 15) * 128;
        const int bm  = (gid >> 4) * 128;

        float* As = sm;            // [2][8][128]
        float* Bs = sm + 2048;     // [2][8][128]

        const int tx = tid & 15;
        const int ty = tid >> 4;

        ull acc2[4][8];
#pragma unroll
        for (int i = 0; i < 4; i++)
#pragma unroll
            for (int j = 0; j < 8; j++) acc2[i][j] = 0ull;

        const int lr = tid >> 1;
        const int lk = (tid & 1) * 4;
        const float* Ap = X + (size_t)(bm + lr) * DIM + lk;
        const float* Bp = Wih + (size_t)(bn + lr) * DIM + lk;

        {
            float4 av = *(const float4*)Ap;
            float4 bv = *(const float4*)Bp;
            As[(lk + 0) * 128 + lr] = av.x; As[(lk + 1) * 128 + lr] = av.y;
            As[(lk + 2) * 128 + lr] = av.z; As[(lk + 3) * 128 + lr] = av.w;
            Bs[(lk + 0) * 128 + lr] = bv.x; Bs[(lk + 1) * 128 + lr] = bv.y;
            Bs[(lk + 2) * 128 + lr] = bv.z; Bs[(lk + 3) * 128 + lr] = bv.w;
        }
        __syncthreads();

        const int NSLAB = DIM / 8;
        for (int s = 0; s < NSLAB; s++) {
            float* Ab = As + (s & 1) * 1024;
            float* Bb = Bs + (s & 1) * 1024;
            float4 avn, bvn;
            if (s + 1 < NSLAB) {
                avn = *(const float4*)(Ap + (s + 1) * 8);
                bvn = *(const float4*)(Bp + (s + 1) * 8);
            }
#pragma unroll
            for (int kk = 0; kk < 8; kk++) {
                const ulonglong2* a01 = (const ulonglong2*)&Ab[kk * 128 + ty * 8];
                ulonglong2 al = a01[0];
                ulonglong2 ah = a01[1];
                ull a2[4] = { al.x, al.y, ah.x, ah.y };
                float4 b0 = *(const float4*)&Bb[kk * 128 + tx * 8];
                float4 b1 = *(const float4*)&Bb[kk * 128 + tx * 8 + 4];
                ull bd[8] = { pk2(b0.x, b0.x), pk2(b0.y, b0.y),
                              pk2(b0.z, b0.z), pk2(b0.w, b0.w),
                              pk2(b1.x, b1.x), pk2(b1.y, b1.y),
                              pk2(b1.z, b1.z), pk2(b1.w, b1.w) };
#pragma unroll
                for (int i2 = 0; i2 < 4; i2++)
#pragma unroll
                    for (int j = 0; j < 8; j++)
                        ffma2(acc2[i2][j], a2[i2], bd[j]);
            }
            if (s + 1 < NSLAB) {
                float* An = As + ((s + 1) & 1) * 1024;
                float* Bn = Bs + ((s + 1) & 1) * 1024;
                An[(lk + 0) * 128 + lr] = avn.x; An[(lk + 1) * 128 + lr] = avn.y;
                An[(lk + 2) * 128 + lr] = avn.z; An[(lk + 3) * 128 + lr] = avn.w;
                Bn[(lk + 0) * 128 + lr] = bvn.x; Bn[(lk + 1) * 128 + lr] = bvn.y;
                Bn[(lk + 2) * 128 + lr] = bvn.z; Bn[(lk + 3) * 128 + lr] = bvn.w;
                __syncthreads();
            }
        }

        const int row0 = bm + ty * 8;
        const int col0 = bn + tx * 8;
        float bias[8];
#pragma unroll
        for (int j = 0; j < 8; j++) bias[j] = bih[col0 + j] + bhh[col0 + j];

#pragma unroll
        for (int i = 0; i < 8; i++) {
            const int i2 = i >> 1;
            const int s  = i & 1;
            float v[8];
#pragma unroll
            for (int j = 0; j < 8; j++) {
                float2 p = upk(acc2[i2][j]);
                v[j] = (s ? p.y : p.x) + bias[j];
            }
            float* dst = &g_gx[(size_t)(row0 + i) * GATES + col0];
            float4 v0 = { v[0], v[1], v[2], v[3] };
            float4 v1 = { v[4], v[5], v[6], v[7] };
            *(float4*)dst       = v0;
            *(float4*)(dst + 4) = v1;
        }

        // publish this tile (all 16 x-tiles of a y-tile => that y-tile ready)
        __syncthreads();
        if (tid == 0) {
            asm volatile("red.release.gpu.global.add.u32 [%0], 1;"
                         :: "l"(&g_ycnt[bm >> 7]) : "memory");
        }
        return;
    }

    // ==================== persistent recurrence (R5 core) ====================
    float* WT  = sm;             // [k:512][c:16]
    float* RED = sm + 8192;      // [ks:8][b*18 + c]
    float* CS  = RED + 4608;     // [bb*4+uu]

    const int u0 = blockIdx.x * 4;

    // load w_hh slice: local col c = uu*4+gate <-> global row gate*512 + u0+uu
    for (int idx = tid; idx < 8192; idx += 256) {
        int c    = idx & 15;
        int k    = idx >> 4;
        int uu   = c >> 2;
        int gate = c & 3;
        int grow = gate * HID + u0 + uu;
        WT[idx] = whh[(size_t)grow * HID + k];
    }
    if (tid < 128) {
        int bb = tid >> 2, uu = tid & 3;
        CS[bb * 4 + uu] = c0[bb * HID + u0 + uu];
    }
    __syncthreads();

    const int ks  = tid >> 5;          // 0..7 K-slice (64 k each)
    const int ln  = tid & 31;
    const int bq  = ln & 7;            // batches 4bq..4bq+3
    const int cq  = ln >> 3;           // cols 4cq..4cq+3
    const int ebb = tid & 31;          // epilogue batch
    const int euu = tid >> 5;          // epilogue unit (tid<128)

    // gx prefetch for t=0 (gated on y-tile 0)
    float gxv[4];
    int   rdy = -1;                    // highest y-tile verified ready
    if (tid < 128) {
        while (ld_acq(&g_ycnt[0]) < 16u) { }
        rdy = 0;
        const size_t base = (size_t)ebb * GATES;
#pragma unroll
        for (int g = 0; g < 4; g++)
            gxv[g] = g_gx[base + g * HID + (u0 + euu)];
    }

    for (int t = 0; t < T_STEPS; t++) {
        const int rb = (t & 1) ^ 1;    // read buffer (h_{t-1})
        const int wb = t & 1;          // write buffer (h_t)

        // per-warp wait: all 128 blocks published h_{t-1}
        if (t > 0) {
            if (ln == 0) {
                const unsigned tgt = 128u * (unsigned)t;
                while (ld_acq(&g_cnt) < tgt) { }
            }
            __syncwarp();
        }

        // 4x4 microtile GEMM; h rows direct from L2 (fresh via ldcg)
        ull acc2[4][2];
#pragma unroll
        for (int i = 0; i < 4; i++) { acc2[i][0] = 0ull; acc2[i][1] = 0ull; }

        const float4* hp = (const float4*)(g_ht[rb] + (ks * 64) * BATCH + bq * 4);
        const float*  wp = WT + (ks * 64) * 16 + cq * 4;
#pragma unroll 16
        for (int k = 0; k < 64; k++) {
            float4 hv = __ldcg(hp); hp += 8;           // +32 floats (one row)
            ulonglong2 wq = *(const ulonglong2*)wp; wp += 16;
            ull h0d = pk2(hv.x, hv.x);
            ull h1d = pk2(hv.y, hv.y);
            ull h2d = pk2(hv.z, hv.z);
            ull h3d = pk2(hv.w, hv.w);
            ffma2(acc2[0][0], h0d, wq.x); ffma2(acc2[0][1], h0d, wq.y);
            ffma2(acc2[1][0], h1d, wq.x); ffma2(acc2[1][1], h1d, wq.y);
            ffma2(acc2[2][0], h2d, wq.x); ffma2(acc2[2][1], h2d, wq.y);
            ffma2(acc2[3][0], h3d, wq.x); ffma2(acc2[3][1], h3d, wq.y);
        }
        // write partials: RED[ks][b:32][c:16 pad 18]
        {
            float* rbuf = RED + ks * 576;
#pragma unroll
            for (int bb = 0; bb < 4; bb++) {
                ull* rp = (ull*)(rbuf + (4 * bq + bb) * 18 + 4 * cq);
                rp[0] = acc2[bb][0];
                rp[1] = acc2[bb][1];
            }
        }
        __syncthreads();

        if (tid < 128) {
            const ull* q = (const ull*)(RED + ebb * 18 + euu * 4);
            ull s01 = 0ull, s23 = 0ull;
#pragma unroll
            for (int kq = 0; kq < 8; kq++) {
                s01 = addf2(s01, q[0]);
                s23 = addf2(s23, q[1]);
                q += 288;   // 576 floats
            }
            float2 p01 = upk(s01);
            float2 p23 = upk(s23);
            float iv = p01.x + gxv[0];
            float fv = p01.y + gxv[1];
            float gv = p23.x + gxv[2];
            float ov = p23.y + gxv[3];
            float it = 1.f / (1.f + __expf(-iv));
            float ft = 1.f / (1.f + __expf(-fv));
            float gt = tanhf(gv);
            float ot = 1.f / (1.f + __expf(-ov));
            float cc  = CS[ebb * 4 + euu];
            float cnv = ft * cc + it * gt;
            CS[ebb * 4 + euu] = cnv;
            float hv = ot * tanhf(cnv);
            g_ht[wb][(u0 + euu) * BATCH + ebb] = hv;   // publish h_t (transposed)
            out[(size_t)t * BATCH * HID + ebb * HID + (u0 + euu)] = hv;
            if (t == T_STEPS - 1) {
                hn[ebb * HID + (u0 + euu)] = hv;
                cn[ebb * HID + (u0 + euu)] = cnv;
            }
        }

        // prefetch gx for t+1 (gated on its y-tile being published)
        if (tid < 128 && t + 1 < T_STEPS) {
            const int yt = (t + 1) >> 2;
            if (yt > rdy) {
                while (ld_acq(&g_ycnt[yt]) < 16u) { }
                rdy = yt;
            }
            const size_t base = ((size_t)(t + 1) * BATCH + ebb) * GATES;
#pragma unroll
            for (int g = 0; g < 4; g++)
                gxv[g] = g_gx[base + g * HID + (u0 + euu)];
        }

        if (t < T_STEPS - 1) {
            __syncthreads();
            if (tid == 0) {
                asm volatile("red.release.gpu.global.add.u32 [%0], 1;"
                             :: "l"(&g_cnt) : "memory");
            }
        }
    }
}

// ---------------------------------------------------------------------------
extern "C" void kernel_launch(void* const* d_in, const int* in_sizes, int n_in,
                              void* d_out, int out_size)
{
    const float* x   = (const float*)d_in[0];
    const float* h0  = (const float*)d_in[1];
    const float* c0  = (const float*)d_in[2];
    const float* wih = (const float*)d_in[3];
    const float* bih = (const float*)d_in[4];
    const float* whh = (const float*)d_in[5];
    const float* bhh = (const float*)d_in[6];

    float* out = (float*)d_out;
    float* hn  = out + (size_t)T_STEPS * BATCH * HID;
    float* cn  = hn + BATCH * HID;

    init_rec<<<64, 256>>>(h0);

    const size_t shmem = SMEM_FLOATS * sizeof(float);
    cudaFuncSetAttribute(mega, cudaFuncAttributeMaxDynamicSharedMemorySize, (int)shmem);
    mega<<<RBLK + NTILE, 256, shmem>>>(x, wih, bih, bhh, c0, whh, out, hn, cn);
}